// round 5
// baseline (speedup 1.0000x reference)
#include <cuda_runtime.h>
#include <cstdint>

// ----------------------------------------------------------------------------
// Problem dims (fixed by dataset)
// ----------------------------------------------------------------------------
#define MDIM 8192   // B*S rows
#define NDIM 4096   // reduction dim
#define KDIM 4096   // output features
#define NGROUPS 32

// GEMM tiling: CTA 128x128, 8 warps (2 wm x 4 wn), warp tile 64x32.
// 2 CTAs per SM (smem 110.6KB each, regs capped at 124).
#define TILE_M  128
#define TILE_KO 128
#define THREADS 256
#define CHUNK   32
#define STAGES  3
#define NCHUNK  (NDIM / CHUNK)   // 128

// Smem strides (floats). 36 = 32 + 4 pad -> fragment LDS addresses are
// (4g + c) mod 32, unique across the warp: conflict-free. (Round-2 proven.)
#define SA_STRIDE 36
#define SB_STRIDE 36
#define SA_FLOATS (TILE_M  * SA_STRIDE)        // 4608
#define SB_FLOATS (TILE_KO * SB_STRIDE)        // 4608
#define STAGE_FLOATS (SA_FLOATS + SB_FLOATS)   // 9216
#define SMEM_BYTES (STAGES * STAGE_FLOATS * 4) // 110592 -> 2 CTAs/SM

// ----------------------------------------------------------------------------
// Device scratch (allocation-free rule: __device__ globals). Plain row-major.
// ----------------------------------------------------------------------------
__device__ float g_Wdeq[(size_t)KDIM * NDIM];   // 64 MB dequant W, tf32-RN
__device__ float g_Xr[(size_t)MDIM * NDIM];     // 134 MB X, tf32-RN

// ----------------------------------------------------------------------------
// Helpers
// ----------------------------------------------------------------------------
__device__ __forceinline__ uint32_t smem_u32(const void* p) {
    uint32_t a;
    asm("{ .reg .u64 t; cvta.to.shared.u64 t, %1; cvt.u32.u64 %0, t; }"
        : "=r"(a) : "l"(p));
    return a;
}

__device__ __forceinline__ float rna_tf32(float x) {
    uint32_t u;
    asm("cvt.rna.tf32.f32 %0, %1;" : "=r"(u) : "f"(x));
    return __uint_as_float(u);
}

__device__ __forceinline__ void cp_async16(uint32_t sdst, const void* gsrc) {
    asm volatile("cp.async.cg.shared.global [%0], [%1], 16;"
                 :: "r"(sdst), "l"(gsrc) : "memory");
}

__device__ __forceinline__ void mma_tf32(float* d, const uint32_t* a,
                                         const uint32_t* b) {
    asm volatile(
        "mma.sync.aligned.m16n8k8.row.col.f32.tf32.tf32.f32 "
        "{%0,%1,%2,%3}, {%4,%5,%6,%7}, {%8,%9}, {%0,%1,%2,%3};"
        : "+f"(d[0]), "+f"(d[1]), "+f"(d[2]), "+f"(d[3])
        : "r"(a[0]), "r"(a[1]), "r"(a[2]), "r"(a[3]), "r"(b[0]), "r"(b[1]));
}

// ----------------------------------------------------------------------------
// Kernel 1: dequantize W (scales/zeros/mu2/mu1 fused), tf32-RN, row-major
// ----------------------------------------------------------------------------
__global__ void dequant_kernel(const int* __restrict__ Wq,
                               const float* __restrict__ scales,
                               const float* __restrict__ zeros,
                               const float* __restrict__ mu1,
                               const float* __restrict__ mu2) {
    int k = blockIdx.x;
    float m2 = mu2[k];
    const int4* wrow = reinterpret_cast<const int4*>(Wq + (size_t)k * NDIM);
    float4* drow = reinterpret_cast<float4*>(g_Wdeq + (size_t)k * NDIM);
    for (int n4 = threadIdx.x; n4 < NDIM / 4; n4 += blockDim.x) {
        int n = n4 * 4;
        int g = n >> 7;
        float s = scales[k * NGROUPS + g] * m2;
        float z = zeros[k * NGROUPS + g];
        int4 q = wrow[n4];
        float4 o;
        o.x = rna_tf32(((float)q.x - z) * s * mu1[n + 0]);
        o.y = rna_tf32(((float)q.y - z) * s * mu1[n + 1]);
        o.z = rna_tf32(((float)q.z - z) * s * mu1[n + 2]);
        o.w = rna_tf32(((float)q.w - z) * s * mu1[n + 3]);
        drow[n4] = o;
    }
}

// ----------------------------------------------------------------------------
// Kernel 2: X -> tf32-RN copy (row-major, fully coalesced)
// ----------------------------------------------------------------------------
__global__ void xprep_kernel(const float* __restrict__ x) {
    const float4* xi = reinterpret_cast<const float4*>(x);
    float4* xo = reinterpret_cast<float4*>(g_Xr);
    size_t i = (size_t)blockIdx.x * blockDim.x + threadIdx.x;
    size_t n4 = (size_t)MDIM * NDIM / 4;
    for (; i < n4; i += (size_t)gridDim.x * blockDim.x) {
        float4 v = xi[i];
        v.x = rna_tf32(v.x); v.y = rna_tf32(v.y);
        v.z = rna_tf32(v.z); v.w = rna_tf32(v.w);
        xo[i] = v;
    }
}

// ----------------------------------------------------------------------------
// Kernel 3: tf32 mma.sync GEMM (round-2 inner structure, 128x128 CTA tile).
// out[m,k] = sum_n Xr[m,n] * Wdeq[k,n] + bias[k]
// ----------------------------------------------------------------------------
__global__ void __launch_bounds__(THREADS, 2)
gemm_kernel(const float* __restrict__ bias, float* __restrict__ out) {
    extern __shared__ float smem[];

    const int tid = threadIdx.x;
    const int wid = tid >> 5;
    const int lane = tid & 31;
    const int g = lane >> 2;      // 0..7
    const int c = lane & 3;       // 0..3
    const int wm = wid & 1;       // warp row (64 rows each)
    const int wn = wid >> 1;      // warp col 0..3 (32 cols each)

    const int k0 = blockIdx.x * TILE_KO;
    const int m0 = blockIdx.y * TILE_M;

    float acc[4][4][4];           // [mi][nj][frag] = 64 regs
    #pragma unroll
    for (int mi = 0; mi < 4; mi++)
        #pragma unroll
        for (int nj = 0; nj < 4; nj++)
            #pragma unroll
            for (int r = 0; r < 4; r++) acc[mi][nj][r] = 0.f;

    // ---- async copy of one chunk into stage buf (R2 pattern) ----
    auto issue = [&](int chunk, int buf) {
        const size_t n0 = (size_t)chunk * CHUNK;
        float* sA = smem + buf * STAGE_FLOATS;
        float* sB = sA + SA_FLOATS;
        #pragma unroll
        for (int i = 0; i < 4; i++) {            // A: 128 rows x 8 float4
            int id = tid + i * THREADS;
            int row = id >> 3, cc = id & 7;
            cp_async16(smem_u32(sA + row * SA_STRIDE + cc * 4),
                       g_Xr + (size_t)(m0 + row) * NDIM + n0 + cc * 4);
        }
        #pragma unroll
        for (int i = 0; i < 4; i++) {            // B: 128 rows x 8 float4
            int id = tid + i * THREADS;
            int row = id >> 3, cc = id & 7;
            cp_async16(smem_u32(sB + row * SB_STRIDE + cc * 4),
                       g_Wdeq + (size_t)(k0 + row) * NDIM + n0 + cc * 4);
        }
        asm volatile("cp.async.commit_group;" ::: "memory");
    };

    // ---- compute one chunk: 4 MMA k-steps, scalar LDS fragments (R2) ----
    auto compute = [&](int buf) {
        const float* sA = smem + buf * STAGE_FLOATS + (wm * 64) * SA_STRIDE;
        const float* sB = smem + buf * STAGE_FLOATS + SA_FLOATS
                               + (wn * 32) * SB_STRIDE;
        #pragma unroll
        for (int ks = 0; ks < 4; ks++) {
            const int col = ks * 8 + c;
            uint32_t a[4][4], b[4][2];
            #pragma unroll
            for (int mi = 0; mi < 4; mi++) {
                const float* ap = sA + (mi * 16 + g) * SA_STRIDE + col;
                a[mi][0] = __float_as_uint(ap[0]);
                a[mi][1] = __float_as_uint(ap[8 * SA_STRIDE]);
                a[mi][2] = __float_as_uint(ap[4]);
                a[mi][3] = __float_as_uint(ap[8 * SA_STRIDE + 4]);
            }
            #pragma unroll
            for (int nj = 0; nj < 4; nj++) {
                const float* bp = sB + (nj * 8 + g) * SB_STRIDE + col;
                b[nj][0] = __float_as_uint(bp[0]);
                b[nj][1] = __float_as_uint(bp[4]);
            }
            #pragma unroll
            for (int mi = 0; mi < 4; mi++)
                #pragma unroll
                for (int nj = 0; nj < 4; nj++)
                    mma_tf32(acc[mi][nj], a[mi], b[nj]);
        }
    };

    // ---- pipeline (R2-faithful: 3 stages, 2 syncs per chunk) ----
    issue(0, 0);
    issue(1, 1);
    for (int i = 0; i < NCHUNK; i++) {
        if (i < NCHUNK - 1)
            asm volatile("cp.async.wait_group 1;" ::: "memory");
        else
            asm volatile("cp.async.wait_group 0;" ::: "memory");
        __syncthreads();
        if (i + 2 < NCHUNK) issue(i + 2, (i + 2) % STAGES);
        compute(i % STAGES);
        __syncthreads();
    }

    // ---- epilogue: bias + float2 stores ----
    #pragma unroll
    for (int nj = 0; nj < 4; nj++) {
        const int col = k0 + wn * 32 + nj * 8 + 2 * c;
        const float2 bv = *reinterpret_cast<const float2*>(bias + col);
        #pragma unroll
        for (int mi = 0; mi < 4; mi++) {
            const int row0 = m0 + wm * 64 + mi * 16 + g;
            float2 v0, v1;
            v0.x = acc[mi][nj][0] + bv.x;  v0.y = acc[mi][nj][1] + bv.y;
            v1.x = acc[mi][nj][2] + bv.x;  v1.y = acc[mi][nj][3] + bv.y;
            *reinterpret_cast<float2*>(out + (size_t)row0 * KDIM + col) = v0;
            *reinterpret_cast<float2*>(out + (size_t)(row0 + 8) * KDIM + col) = v1;
        }
    }
}

// ----------------------------------------------------------------------------
// Host launch
// ----------------------------------------------------------------------------
extern "C" void kernel_launch(void* const* d_in, const int* in_sizes, int n_in,
                              void* d_out, int out_size) {
    const float* x      = (const float*)d_in[0];
    const int*   Wq     = (const int*)d_in[1];
    const float* scales = (const float*)d_in[2];
    const float* zeros  = (const float*)d_in[3];
    const float* mu1    = (const float*)d_in[4];
    const float* mu2    = (const float*)d_in[5];
    const float* bias   = (const float*)d_in[6];
    float* out = (float*)d_out;

    dequant_kernel<<<KDIM, 256>>>(Wq, scales, zeros, mu1, mu2);
    xprep_kernel<<<4096, 256>>>(x);

    cudaFuncSetAttribute(gemm_kernel,
                         cudaFuncAttributeMaxDynamicSharedMemorySize,
                         SMEM_BYTES);
    dim3 grid(KDIM / TILE_KO, MDIM / TILE_M);   // (32, 64)
    gemm_kernel<<<grid, THREADS, SMEM_BYTES>>>(bias, out);
}

// round 6
// speedup vs baseline: 1.5590x; 1.5590x over previous
#include <cuda_runtime.h>
#include <cstdint>

// ----------------------------------------------------------------------------
// Problem dims (fixed by dataset)
// ----------------------------------------------------------------------------
#define MDIM 8192   // B*S rows
#define NDIM 4096   // reduction dim
#define KDIM 4096   // output features
#define NGROUPS 32

// GEMM tiling (round-2 proven): CTA 128x256, 8 warps (2 wm x 4 wn), warp 64x64
#define TILE_M  128
#define TILE_KO 256
#define THREADS 256
#define CHUNK   32
#define STAGES  4
#define NCHUNK  (NDIM / CHUNK)   // 128

// Smem strides (floats). 36 = 32 + 4 pad -> fragment LDS addresses are
// (4g + c) mod 32, unique across the warp: conflict-free. (Round-2 proven.)
#define SA_STRIDE 36
#define SB_STRIDE 36
#define SA_FLOATS (TILE_M  * SA_STRIDE)        // 4608
#define SB_FLOATS (TILE_KO * SB_STRIDE)        // 9216
#define STAGE_FLOATS (SA_FLOATS + SB_FLOATS)   // 13824
#define SMEM_BYTES (STAGES * STAGE_FLOATS * 4) // 221184 (fits 228KB, 1 CTA/SM)

// ----------------------------------------------------------------------------
// Device scratch (allocation-free rule: __device__ global)
// ----------------------------------------------------------------------------
__device__ float g_Wdeq[(size_t)KDIM * NDIM];   // 64 MB dequant W, tf32-RN

// ----------------------------------------------------------------------------
// Helpers
// ----------------------------------------------------------------------------
__device__ __forceinline__ uint32_t smem_u32(const void* p) {
    uint32_t a;
    asm("{ .reg .u64 t; cvta.to.shared.u64 t, %1; cvt.u32.u64 %0, t; }"
        : "=r"(a) : "l"(p));
    return a;
}

__device__ __forceinline__ uint32_t rna_tf32_bits(float x) {
    uint32_t u;
    asm("cvt.rna.tf32.f32 %0, %1;" : "=r"(u) : "f"(x));
    return u;
}
__device__ __forceinline__ float rna_tf32(float x) {
    return __uint_as_float(rna_tf32_bits(x));
}

__device__ __forceinline__ void cp_async16(uint32_t sdst, const void* gsrc) {
    asm volatile("cp.async.cg.shared.global [%0], [%1], 16;"
                 :: "r"(sdst), "l"(gsrc) : "memory");
}

__device__ __forceinline__ void mma_tf32(float* d, const uint32_t* a,
                                         const uint32_t* b) {
    asm volatile(
        "mma.sync.aligned.m16n8k8.row.col.f32.tf32.tf32.f32 "
        "{%0,%1,%2,%3}, {%4,%5,%6,%7}, {%8,%9}, {%0,%1,%2,%3};"
        : "+f"(d[0]), "+f"(d[1]), "+f"(d[2]), "+f"(d[3])
        : "r"(a[0]), "r"(a[1]), "r"(a[2]), "r"(a[3]), "r"(b[0]), "r"(b[1]));
}

// ----------------------------------------------------------------------------
// Kernel 1: dequantize W (scales/zeros/mu2/mu1 fused), tf32-RN (round-2)
// ----------------------------------------------------------------------------
__global__ void dequant_kernel(const int* __restrict__ Wq,
                               const float* __restrict__ scales,
                               const float* __restrict__ zeros,
                               const float* __restrict__ mu1,
                               const float* __restrict__ mu2) {
    int k = blockIdx.x;
    float m2 = mu2[k];
    const int4* wrow = reinterpret_cast<const int4*>(Wq + (size_t)k * NDIM);
    float4* drow = reinterpret_cast<float4*>(g_Wdeq + (size_t)k * NDIM);
    for (int n4 = threadIdx.x; n4 < NDIM / 4; n4 += blockDim.x) {
        int n = n4 * 4;
        int g = n >> 7;
        float s = scales[k * NGROUPS + g] * m2;
        float z = zeros[k * NGROUPS + g];
        int4 q = wrow[n4];
        float4 o;
        o.x = rna_tf32(((float)q.x - z) * s * mu1[n + 0]);
        o.y = rna_tf32(((float)q.y - z) * s * mu1[n + 1]);
        o.z = rna_tf32(((float)q.z - z) * s * mu1[n + 2]);
        o.w = rna_tf32(((float)q.w - z) * s * mu1[n + 3]);
        drow[n4] = o;
    }
}

// ----------------------------------------------------------------------------
// Kernel 2: tf32 mma.sync GEMM — round-2 structure + intra-chunk fragment
// double-buffering + 4-stage/1-sync pipeline.
// out[m,k] = sum_n X[m,n] * Wdeq[k,n] + bias[k]
// ----------------------------------------------------------------------------
__global__ void __launch_bounds__(THREADS, 1)
gemm_kernel(const float* __restrict__ x,
            const float* __restrict__ bias,
            float* __restrict__ out) {
    extern __shared__ float smem[];

    const int tid = threadIdx.x;
    const int wid = tid >> 5;
    const int lane = tid & 31;
    const int g = lane >> 2;      // 0..7
    const int c = lane & 3;       // 0..3
    const int wm = wid & 1;       // warp row (64 rows)
    const int wn = wid >> 1;      // warp col (64 cols)

    const int k0 = blockIdx.x * TILE_KO;
    const int m0 = blockIdx.y * TILE_M;

    float acc[4][8][4];
    #pragma unroll
    for (int mi = 0; mi < 4; mi++)
        #pragma unroll
        for (int ni = 0; ni < 8; ni++)
            #pragma unroll
            for (int r = 0; r < 4; r++) acc[mi][ni][r] = 0.f;

    // ---- async copy of one chunk into stage buf (R2 pattern) ----
    auto issue = [&](int chunk, int buf) {
        const size_t n0 = (size_t)chunk * CHUNK;
        float* sA = smem + buf * STAGE_FLOATS;
        float* sB = sA + SA_FLOATS;
        #pragma unroll
        for (int i = 0; i < 4; i++) {            // A: 128 rows x 8 float4
            int id = tid + i * THREADS;
            int row = id >> 3, cc = id & 7;
            cp_async16(smem_u32(sA + row * SA_STRIDE + cc * 4),
                       x + (size_t)(m0 + row) * NDIM + n0 + cc * 4);
        }
        #pragma unroll
        for (int i = 0; i < 8; i++) {            // B: 256 rows x 8 float4
            int id = tid + i * THREADS;
            int row = id >> 3, cc = id & 7;
            cp_async16(smem_u32(sB + row * SB_STRIDE + cc * 4),
                       g_Wdeq + (size_t)(k0 + row) * NDIM + n0 + cc * 4);
        }
        asm volatile("cp.async.commit_group;" ::: "memory");
    };

    // ---- compute one chunk: 4 k-steps, fragments double-buffered ----
    auto compute = [&](int buf) {
        const float* sA = smem + buf * STAGE_FLOATS + (wm * 64) * SA_STRIDE;
        const float* sB = smem + buf * STAGE_FLOATS + SA_FLOATS
                               + (wn * 64) * SB_STRIDE;

        uint32_t a[2][4][4], b[2][8][2];   // ping-pong fragment sets

        auto load_frags = [&](int ks, int set) {
            const int col = ks * 8 + c;
            #pragma unroll
            for (int mi = 0; mi < 4; mi++) {
                const float* ap = sA + (mi * 16 + g) * SA_STRIDE + col;
                a[set][mi][0] = rna_tf32_bits(ap[0]);
                a[set][mi][1] = rna_tf32_bits(ap[8 * SA_STRIDE]);
                a[set][mi][2] = rna_tf32_bits(ap[4]);
                a[set][mi][3] = rna_tf32_bits(ap[8 * SA_STRIDE + 4]);
            }
            #pragma unroll
            for (int ni = 0; ni < 8; ni++) {
                const float* bp = sB + (ni * 8 + g) * SB_STRIDE + col;
                b[set][ni][0] = __float_as_uint(bp[0]);   // W pre-rounded
                b[set][ni][1] = __float_as_uint(bp[4]);
            }
        };

        load_frags(0, 0);
        #pragma unroll
        for (int ks = 0; ks < 4; ks++) {
            const int cur = ks & 1;
            if (ks < 3) load_frags(ks + 1, cur ^ 1);   // prefetch next k-step
            #pragma unroll
            for (int mi = 0; mi < 4; mi++)
                #pragma unroll
                for (int ni = 0; ni < 8; ni++)
                    mma_tf32(acc[mi][ni], a[cur][mi], b[cur][ni]);
        }
    };

    // ---- pipeline: 4 stages, ONE sync per chunk ----
    issue(0, 0);
    issue(1, 1);
    issue(2, 2);
    for (int i = 0; i < NCHUNK; i++) {
        if (i < NCHUNK - 2)
            asm volatile("cp.async.wait_group 2;" ::: "memory");
        else
            asm volatile("cp.async.wait_group 0;" ::: "memory");
        __syncthreads();
        if (i + 3 < NCHUNK) issue(i + 3, (i + 3) & 3);
        compute(i & 3);
    }

    // ---- epilogue: bias + float2 stores (R2) ----
    #pragma unroll
    for (int ni = 0; ni < 8; ni++) {
        const int col = k0 + wn * 64 + ni * 8 + 2 * c;
        const float2 bv = *reinterpret_cast<const float2*>(bias + col);
        #pragma unroll
        for (int mi = 0; mi < 4; mi++) {
            const int row0 = m0 + wm * 64 + mi * 16 + g;
            float2 v0, v1;
            v0.x = acc[mi][ni][0] + bv.x;  v0.y = acc[mi][ni][1] + bv.y;
            v1.x = acc[mi][ni][2] + bv.x;  v1.y = acc[mi][ni][3] + bv.y;
            *reinterpret_cast<float2*>(out + (size_t)row0 * KDIM + col) = v0;
            *reinterpret_cast<float2*>(out + (size_t)(row0 + 8) * KDIM + col) = v1;
        }
    }
}

// ----------------------------------------------------------------------------
// Host launch
// ----------------------------------------------------------------------------
extern "C" void kernel_launch(void* const* d_in, const int* in_sizes, int n_in,
                              void* d_out, int out_size) {
    const float* x      = (const float*)d_in[0];
    const int*   Wq     = (const int*)d_in[1];
    const float* scales = (const float*)d_in[2];
    const float* zeros  = (const float*)d_in[3];
    const float* mu1    = (const float*)d_in[4];
    const float* mu2    = (const float*)d_in[5];
    const float* bias   = (const float*)d_in[6];
    float* out = (float*)d_out;

    dequant_kernel<<<KDIM, 256>>>(Wq, scales, zeros, mu1, mu2);

    cudaFuncSetAttribute(gemm_kernel,
                         cudaFuncAttributeMaxDynamicSharedMemorySize,
                         SMEM_BYTES);
    dim3 grid(KDIM / TILE_KO, MDIM / TILE_M);   // (16, 64)
    gemm_kernel<<<grid, THREADS, SMEM_BYTES>>>(x, bias, out);
}

// round 7
// speedup vs baseline: 3.1141x; 1.9975x over previous
#include <cuda_runtime.h>
#include <cuda_fp16.h>
#include <cstdint>

// ----------------------------------------------------------------------------
// Problem dims (fixed by dataset)
// ----------------------------------------------------------------------------
#define MDIM 8192   // B*S rows
#define NDIM 4096   // reduction dim
#define KDIM 4096   // output features
#define NGROUPS 32

// GEMM tiling: CTA 128x256, 8 warps (2 wm x 4 wn), warp tile 64x64.
// fp16 m16n8k16: chunk = 64 k-elems, 4 k-steps of 16 per chunk.
#define TILE_M  128
#define TILE_KO 256
#define THREADS 256
#define CHUNK   64
#define STAGES  4
#define NCHUNK  (NDIM / CHUNK)   // 64

// Smem rows: CHUNK halves of data + 8 halves pad -> stride 72 halves (144B).
// Fragment LDS word addr = row*36 + ks*8 + c (+4); across a warp the words are
// (4g + c) mod 32 (+4) -> all 32 lanes distinct: conflict-free.
#define ROW_HALves 72
#define ROW_WORDS  36                         // 36 4-byte words per row
#define SA_WORDS (TILE_M  * ROW_WORDS)        // 4608
#define SB_WORDS (TILE_KO * ROW_WORDS)        // 9216
#define STAGE_WORDS (SA_WORDS + SB_WORDS)     // 13824
#define SMEM_BYTES (STAGES * STAGE_WORDS * 4) // 221184 (1 CTA/SM)

// ----------------------------------------------------------------------------
// Device scratch (allocation-free rule: __device__ globals)
// ----------------------------------------------------------------------------
__device__ __half g_Wh[(size_t)KDIM * NDIM];  // 32 MB dequant W, fp16-RN
__device__ __half g_Xh[(size_t)MDIM * NDIM];  // 67 MB X, fp16-RN

// ----------------------------------------------------------------------------
// Helpers
// ----------------------------------------------------------------------------
__device__ __forceinline__ uint32_t smem_u32(const void* p) {
    uint32_t a;
    asm("{ .reg .u64 t; cvta.to.shared.u64 t, %1; cvt.u32.u64 %0, t; }"
        : "=r"(a) : "l"(p));
    return a;
}

__device__ __forceinline__ void cp_async16(uint32_t sdst, const void* gsrc) {
    asm volatile("cp.async.cg.shared.global [%0], [%1], 16;"
                 :: "r"(sdst), "l"(gsrc) : "memory");
}

__device__ __forceinline__ void mma_f16(float* d, const uint32_t* a,
                                        const uint32_t* b) {
    asm volatile(
        "mma.sync.aligned.m16n8k16.row.col.f32.f16.f16.f32 "
        "{%0,%1,%2,%3}, {%4,%5,%6,%7}, {%8,%9}, {%0,%1,%2,%3};"
        : "+f"(d[0]), "+f"(d[1]), "+f"(d[2]), "+f"(d[3])
        : "r"(a[0]), "r"(a[1]), "r"(a[2]), "r"(a[3]), "r"(b[0]), "r"(b[1]));
}

__device__ __forceinline__ uint32_t pack_h2(float lo, float hi) {
    __half2 h = __halves2half2(__float2half_rn(lo), __float2half_rn(hi));
    return *reinterpret_cast<uint32_t*>(&h);
}

// ----------------------------------------------------------------------------
// Kernel 1: dequantize W (scales/zeros/mu2/mu1 fused) -> fp16
// ----------------------------------------------------------------------------
__global__ void dequant_kernel(const int* __restrict__ Wq,
                               const float* __restrict__ scales,
                               const float* __restrict__ zeros,
                               const float* __restrict__ mu1,
                               const float* __restrict__ mu2) {
    int k = blockIdx.x;
    float m2 = mu2[k];
    const int4* wrow = reinterpret_cast<const int4*>(Wq + (size_t)k * NDIM);
    uint2* drow = reinterpret_cast<uint2*>(g_Wh + (size_t)k * NDIM);
    for (int n4 = threadIdx.x; n4 < NDIM / 4; n4 += blockDim.x) {
        int n = n4 * 4;
        int g = n >> 7;
        float s = scales[k * NGROUPS + g] * m2;
        float z = zeros[k * NGROUPS + g];
        int4 q = wrow[n4];
        uint2 o;
        o.x = pack_h2(((float)q.x - z) * s * mu1[n + 0],
                      ((float)q.y - z) * s * mu1[n + 1]);
        o.y = pack_h2(((float)q.z - z) * s * mu1[n + 2],
                      ((float)q.w - z) * s * mu1[n + 3]);
        drow[n4] = o;
    }
}

// ----------------------------------------------------------------------------
// Kernel 2: X -> fp16-RN copy
// ----------------------------------------------------------------------------
__global__ void xprep_kernel(const float* __restrict__ x) {
    const float4* xi = reinterpret_cast<const float4*>(x);
    uint2* xo = reinterpret_cast<uint2*>(g_Xh);
    size_t n4 = (size_t)MDIM * NDIM / 4;
    for (size_t i = (size_t)blockIdx.x * blockDim.x + threadIdx.x; i < n4;
         i += (size_t)gridDim.x * blockDim.x) {
        float4 v = xi[i];
        uint2 o;
        o.x = pack_h2(v.x, v.y);
        o.y = pack_h2(v.z, v.w);
        xo[i] = o;
    }
}

// ----------------------------------------------------------------------------
// Kernel 3: fp16 mma.sync GEMM. out[m,k] = sum_n X[m,n]*W[k,n] + bias[k]
// ----------------------------------------------------------------------------
__global__ void __launch_bounds__(THREADS, 1)
gemm_kernel(const float* __restrict__ bias, float* __restrict__ out) {
    extern __shared__ uint32_t smem[];   // word-addressed

    const int tid = threadIdx.x;
    const int wid = tid >> 5;
    const int lane = tid & 31;
    const int g = lane >> 2;      // 0..7
    const int c = lane & 3;       // 0..3
    const int wm = wid & 1;       // warp row (64 rows)
    const int wn = wid >> 1;      // warp col (64 cols)

    const int k0 = blockIdx.x * TILE_KO;
    const int m0 = blockIdx.y * TILE_M;

    float acc[4][8][4];
    #pragma unroll
    for (int mi = 0; mi < 4; mi++)
        #pragma unroll
        for (int ni = 0; ni < 8; ni++)
            #pragma unroll
            for (int r = 0; r < 4; r++) acc[mi][ni][r] = 0.f;

    const uint32_t smem_base = smem_u32(smem);

    // ---- async copy of one chunk (64 halves = 128B data per row) ----
    auto issue = [&](int chunk, int buf) {
        const size_t n0 = (size_t)chunk * CHUNK;
        const uint32_t sA = smem_base + buf * STAGE_WORDS * 4;
        const uint32_t sB = sA + SA_WORDS * 4;
        #pragma unroll
        for (int i = 0; i < 4; i++) {            // A: 128 rows x 8 x 16B
            int id = tid + i * THREADS;
            int row = id >> 3, cc = id & 7;
            cp_async16(sA + row * 144 + cc * 16,
                       g_Xh + (size_t)(m0 + row) * NDIM + n0 + cc * 8);
        }
        #pragma unroll
        for (int i = 0; i < 8; i++) {            // B: 256 rows x 8 x 16B
            int id = tid + i * THREADS;
            int row = id >> 3, cc = id & 7;
            cp_async16(sB + row * 144 + cc * 16,
                       g_Wh + (size_t)(k0 + row) * NDIM + n0 + cc * 8);
        }
        asm volatile("cp.async.commit_group;" ::: "memory");
    };

    // ---- compute one chunk: 4 k16-steps, fragments double-buffered ----
    auto compute = [&](int buf) {
        const uint32_t* uA = smem + buf * STAGE_WORDS + (wm * 64) * ROW_WORDS;
        const uint32_t* uB = smem + buf * STAGE_WORDS + SA_WORDS
                                  + (wn * 64) * ROW_WORDS;

        uint32_t a[2][4][4], b[2][8][2];   // ping-pong fragment sets

        auto load_frags = [&](int ks, int set) {
            const int col = ks * 8 + c;
            #pragma unroll
            for (int mi = 0; mi < 4; mi++) {
                const uint32_t* ap = uA + (mi * 16 + g) * ROW_WORDS + col;
                a[set][mi][0] = ap[0];
                a[set][mi][1] = ap[8 * ROW_WORDS];
                a[set][mi][2] = ap[4];
                a[set][mi][3] = ap[8 * ROW_WORDS + 4];
            }
            #pragma unroll
            for (int ni = 0; ni < 8; ni++) {
                const uint32_t* bp = uB + (ni * 8 + g) * ROW_WORDS + col;
                b[set][ni][0] = bp[0];
                b[set][ni][1] = bp[4];
            }
        };

        load_frags(0, 0);
        #pragma unroll
        for (int ks = 0; ks < 4; ks++) {
            const int cur = ks & 1;
            if (ks < 3) load_frags(ks + 1, cur ^ 1);
            #pragma unroll
            for (int mi = 0; mi < 4; mi++)
                #pragma unroll
                for (int ni = 0; ni < 8; ni++)
                    mma_f16(acc[mi][ni], a[cur][mi], b[cur][ni]);
        }
    };

    // ---- pipeline: 4 stages, one sync per chunk ----
    issue(0, 0);
    issue(1, 1);
    issue(2, 2);
    for (int i = 0; i < NCHUNK; i++) {
        if (i < NCHUNK - 2)
            asm volatile("cp.async.wait_group 2;" ::: "memory");
        else
            asm volatile("cp.async.wait_group 0;" ::: "memory");
        __syncthreads();
        if (i + 3 < NCHUNK) issue(i + 3, (i + 3) & 3);
        compute(i & 3);
    }

    // ---- epilogue: bias + float2 stores ----
    #pragma unroll
    for (int ni = 0; ni < 8; ni++) {
        const int col = k0 + wn * 64 + ni * 8 + 2 * c;
        const float2 bv = *reinterpret_cast<const float2*>(bias + col);
        #pragma unroll
        for (int mi = 0; mi < 4; mi++) {
            const int row0 = m0 + wm * 64 + mi * 16 + g;
            float2 v0, v1;
            v0.x = acc[mi][ni][0] + bv.x;  v0.y = acc[mi][ni][1] + bv.y;
            v1.x = acc[mi][ni][2] + bv.x;  v1.y = acc[mi][ni][3] + bv.y;
            *reinterpret_cast<float2*>(out + (size_t)row0 * KDIM + col) = v0;
            *reinterpret_cast<float2*>(out + (size_t)(row0 + 8) * KDIM + col) = v1;
        }
    }
}

// ----------------------------------------------------------------------------
// Host launch
// ----------------------------------------------------------------------------
extern "C" void kernel_launch(void* const* d_in, const int* in_sizes, int n_in,
                              void* d_out, int out_size) {
    const float* x      = (const float*)d_in[0];
    const int*   Wq     = (const int*)d_in[1];
    const float* scales = (const float*)d_in[2];
    const float* zeros  = (const float*)d_in[3];
    const float* mu1    = (const float*)d_in[4];
    const float* mu2    = (const float*)d_in[5];
    const float* bias   = (const float*)d_in[6];
    float* out = (float*)d_out;

    dequant_kernel<<<KDIM, 256>>>(Wq, scales, zeros, mu1, mu2);
    xprep_kernel<<<4096, 256>>>(x);

    cudaFuncSetAttribute(gemm_kernel,
                         cudaFuncAttributeMaxDynamicSharedMemorySize,
                         SMEM_BYTES);
    dim3 grid(KDIM / TILE_KO, MDIM / TILE_M);   // (16, 64)
    gemm_kernel<<<grid, THREADS, SMEM_BYTES>>>(bias, out);
}